// round 15
// baseline (speedup 1.0000x reference)
#include <cuda_runtime.h>
#include <cuda_fp16.h>
#include <math_constants.h>
#include <cstdint>

#define NN   50000
#define EE   800000
#define INF_ 256
#define OUTF 64
#define NHEAD 4
#define FEAT (NHEAD*OUTF)   // 256
#define ALPHA 0.2f

// -------- device scratch (static; allocation-free; zero-initialized) --------
__device__ __half g_hh[(size_t)NN * FEAT];   // projected features, fp16
__device__ float g_hl[NN * NHEAD];
__device__ float g_hr[NN * NHEAD];
__device__ uint2 g_Wf[NHEAD * 16 * 8 * 32];  // W in fp16 mma-fragment order (128KB)
__device__ int   g_deg[NN];                  // reset by aggregate each replay
__device__ int   g_rowptr[NN + 1];
__device__ int   g_cursor[NN];
__device__ int   g_cols[EE];

#define HIST_BLOCKS 3125
#define WF_BLOCKS 64
#define GEMM_BLOCKS 1564   // 4 heads x 391 mtiles
#define SCAN_TILE 2048
#define SCAN_BLOCKS 25     // ceil(50000/2048)

// ===== launch 1: edge histogram + W fragment prep (blockIdx split) =====
__global__ __launch_bounds__(256) void hist_prep_kernel(const int* __restrict__ edge,
                                                        const float* __restrict__ W) {
    int b = blockIdx.x;
    if (b < HIST_BLOCKS) {
        int e = b * 256 + threadIdx.x;
        if (e < EE) atomicAdd(&g_deg[edge[e]], 1);
    } else {
        int idx = (b - HIST_BLOCKS) * 256 + threadIdx.x;
        if (idx >= NHEAD * 16 * 8 * 32) return;
        int lane = idx & 31;
        int nblk = (idx >> 5) & 7;
        int ks   = (idx >> 8) & 15;
        int hb   = idx >> 12;
        int g = lane >> 2, tg = lane & 3;
        int n = hb * OUTF + nblk * 8 + g;
        int k0 = ks * 16 + 2 * tg;
        __half2 b0 = __floats2half2_rn(W[(size_t)k0 * FEAT + n],
                                       W[(size_t)(k0 + 1) * FEAT + n]);
        __half2 b1 = __floats2half2_rn(W[(size_t)(k0 + 8) * FEAT + n],
                                       W[(size_t)(k0 + 9) * FEAT + n]);
        g_Wf[idx] = make_uint2(*(unsigned*)&b0, *(unsigned*)&b1);
    }
}

// ===== launch 2: PARALLEL scan — 25 independent blocks, no inter-block comms =====
__global__ __launch_bounds__(256) void scan_parallel_kernel() {
    __shared__ int s_warp[8];
    __shared__ int s_off;
    int b = blockIdx.x;
    int tid = threadIdx.x;
    int lane = tid & 31, w = tid >> 5;
    int tile0 = b * SCAN_TILE;

    int part = 0;
    for (int i = tid; i < tile0; i += 256) part += g_deg[i];
#pragma unroll
    for (int o = 16; o; o >>= 1) part += __shfl_xor_sync(0xffffffffu, part, o);
    if (lane == 0) s_warp[w] = part;
    __syncthreads();
    if (tid == 0) {
        int s = 0;
#pragma unroll
        for (int k = 0; k < 8; k++) s += s_warp[k];
        s_off = s;
    }
    __syncthreads();
    int offset = s_off;
    __syncthreads();   // s_warp reused below

    int i0 = tile0 + tid * 8;
    int v[8];
#pragma unroll
    for (int j = 0; j < 8; j++) {
        int i = i0 + j;
        v[j] = (i < NN) ? g_deg[i] : 0;
    }
#pragma unroll
    for (int j = 1; j < 8; j++) v[j] += v[j - 1];
    int x = v[7];
#pragma unroll
    for (int o = 1; o < 32; o <<= 1) {
        int y = __shfl_up_sync(0xffffffffu, x, o);
        if (lane >= o) x += y;
    }
    if (lane == 31) s_warp[w] = x;
    __syncthreads();
    if (w == 0 && lane < 8) {
        int s = s_warp[lane];
#pragma unroll
        for (int o = 1; o < 8; o <<= 1) {
            int y = __shfl_up_sync(0x000000ffu, s, o);
            if (lane >= o) s += y;
        }
        s_warp[lane] = s;
    }
    __syncthreads();
    int off = offset + (x - v[7]) + (w > 0 ? s_warp[w - 1] : 0);

#pragma unroll
    for (int j = 0; j < 8; j++) {
        int i = i0 + j;
        if (i < NN) {
            g_rowptr[i + 1] = off + v[j];
            g_cursor[i] = off + (j > 0 ? v[j - 1] : 0);
        }
    }
    if (b == 0 && tid == 0) g_rowptr[0] = 0;
}

// ===== launch 3: fp16 mma GEMM (+fused logits) || CSR scatter (blockIdx split) =====
#define A_STAGE_B 8224   // bytes (2 kst * 4112)

__device__ __forceinline__ void mma_f16(float c[4], unsigned a0, unsigned a1,
                                        unsigned a2, unsigned a3,
                                        unsigned b0, unsigned b1) {
    asm volatile(
        "mma.sync.aligned.m16n8k16.row.col.f32.f16.f16.f32 "
        "{%0,%1,%2,%3}, {%4,%5,%6,%7}, {%8,%9}, {%0,%1,%2,%3};"
        : "+f"(c[0]), "+f"(c[1]), "+f"(c[2]), "+f"(c[3])
        : "r"(a0), "r"(a1), "r"(a2), "r"(a3), "r"(b0), "r"(b1));
}

__device__ __forceinline__ int a_sts_off(int r, int c4) {
    return ((c4 >> 4) ? 4112 : 0) + (r >> 4) * 512 +
           (((r & 7) * 4 + ((c4 & 7) >> 1)) << 4) + (((c4 >> 3) & 1) << 3) +
           (((r >> 3) & 1) << 2);
}

__global__ __launch_bounds__(128, 4) void gemm_scatter_kernel(
    const float* __restrict__ X,
    const float* __restrict__ al, const float* __restrict__ ar,
    const int* __restrict__ edge) {
    __shared__ __align__(16) char sAbuf[2 * A_STAGE_B];

    if (blockIdx.x >= GEMM_BLOCKS) {
        int e = (blockIdx.x - GEMM_BLOCKS) * 128 + threadIdx.x;
        if (e < EE) {
            int r = edge[e];
            int c = edge[EE + e];
            int pos = atomicAdd(&g_cursor[r], 1);
            g_cols[pos] = c;
        }
        return;
    }

    int tid = threadIdx.x;
    int lane = tid & 31;
    int wid = tid >> 5;
    int wm = wid >> 1, wn = wid & 1;
    int g = lane >> 2, tg = lane & 3;
    int hb = blockIdx.x & 3;                 // head
    int bm = (blockIdx.x >> 2) * 128;
    int bn = hb * OUTF;

    float acc[4][4][4];
#pragma unroll
    for (int mt = 0; mt < 4; mt++)
#pragma unroll
        for (int nt = 0; nt < 4; nt++)
#pragma unroll
            for (int q = 0; q < 4; q++) acc[mt][nt][q] = 0.f;

    const uint2* Wfb = g_Wf + hb * (16 * 8 * 32);

    uint2 ra[8];
#pragma unroll
    for (int i = 0; i < 8; i++) {
        int f = tid + i * 128;
        int r = f >> 3, c4 = (f & 7) * 4;
        int row = bm + r;
        float4 t = (row < NN) ? *(const float4*)(X + (size_t)row * INF_ + c4)
                              : make_float4(0.f, 0.f, 0.f, 0.f);
        __half2 h0 = __floats2half2_rn(t.x, t.y);
        __half2 h1 = __floats2half2_rn(t.z, t.w);
        ra[i] = make_uint2(*(unsigned*)&h0, *(unsigned*)&h1);
    }
#pragma unroll
    for (int i = 0; i < 8; i++) {
        int f = tid + i * 128;
        int r = f >> 3, c4 = (f & 7) * 4;
        char* p = sAbuf + a_sts_off(r, c4);
        *(unsigned*)p = ra[i].x;
        *(unsigned*)(p + 16) = ra[i].y;
    }
    uint2 bq[4], bqn[4];
#pragma unroll
    for (int nt = 0; nt < 4; nt++)
        bq[nt] = Wfb[(0 * 8 + wn * 4 + nt) * 32 + lane];
    __syncthreads();

    for (int kt = 0; kt < 8; kt++) {
        int st = kt & 1;
        const char* As = sAbuf + st * A_STAGE_B;
        if (kt < 7) {
            int k0 = (kt + 1) * 32;
#pragma unroll
            for (int i = 0; i < 8; i++) {
                int f = tid + i * 128;
                int r = f >> 3, c4 = (f & 7) * 4;
                int row = bm + r;
                float4 t = (row < NN) ? *(const float4*)(X + (size_t)row * INF_ + k0 + c4)
                                      : make_float4(0.f, 0.f, 0.f, 0.f);
                __half2 h0 = __floats2half2_rn(t.x, t.y);
                __half2 h1 = __floats2half2_rn(t.z, t.w);
                ra[i] = make_uint2(*(unsigned*)&h0, *(unsigned*)&h1);
            }
        }
#pragma unroll
        for (int kst = 0; kst < 2; kst++) {
            int ks = kt * 2 + kst;
            if (ks < 15) {
#pragma unroll
                for (int nt = 0; nt < 4; nt++)
                    bqn[nt] = Wfb[((ks + 1) * 8 + wn * 4 + nt) * 32 + lane];
            }
            uint4 af[4];
#pragma unroll
            for (int mt = 0; mt < 4; mt++)
                af[mt] = *(const uint4*)(As + kst * 4112 + (wm * 4 + mt) * 512 +
                                         (g * 4 + tg) * 16);
#pragma unroll
            for (int mt = 0; mt < 4; mt++)
#pragma unroll
                for (int nt = 0; nt < 4; nt++)
                    mma_f16(acc[mt][nt], af[mt].x, af[mt].y, af[mt].z, af[mt].w,
                            bq[nt].x, bq[nt].y);
#pragma unroll
            for (int nt = 0; nt < 4; nt++) bq[nt] = bqn[nt];
        }
        if (kt < 7) {
            char* dA = sAbuf + (1 - st) * A_STAGE_B;
#pragma unroll
            for (int i = 0; i < 8; i++) {
                int f = tid + i * 128;
                int r = f >> 3, c4 = (f & 7) * 4;
                char* p = dA + a_sts_off(r, c4);
                *(unsigned*)p = ra[i].x;
                *(unsigned*)(p + 16) = ra[i].y;
            }
        }
        __syncthreads();
    }

    // epilogue: store h fp16; fused hl/hr logits
    const float* alh = al + hb * OUTF;
    const float* arh = ar + hb * OUTF;
    float plv[4][2] = {{0.f,0.f},{0.f,0.f},{0.f,0.f},{0.f,0.f}};
    float prv[4][2] = {{0.f,0.f},{0.f,0.f},{0.f,0.f},{0.f,0.f}};

#pragma unroll
    for (int mt = 0; mt < 4; mt++) {
#pragma unroll
        for (int nt = 0; nt < 4; nt++) {
            int row0 = bm + wm * 64 + mt * 16 + g;
            int cl = wn * 32 + nt * 8 + tg * 2;
            int col = bn + cl;
            if (row0 < NN)
                *(__half2*)(g_hh + (size_t)row0 * FEAT + col) =
                    __floats2half2_rn(acc[mt][nt][0], acc[mt][nt][1]);
            if (row0 + 8 < NN)
                *(__half2*)(g_hh + (size_t)(row0 + 8) * FEAT + col) =
                    __floats2half2_rn(acc[mt][nt][2], acc[mt][nt][3]);
            float a0l = alh[cl], a1l = alh[cl + 1];
            float a0r = arh[cl], a1r = arh[cl + 1];
            plv[mt][0] = fmaf(a0l, acc[mt][nt][0], fmaf(a1l, acc[mt][nt][1], plv[mt][0]));
            plv[mt][1] = fmaf(a0l, acc[mt][nt][2], fmaf(a1l, acc[mt][nt][3], plv[mt][1]));
            prv[mt][0] = fmaf(a0r, acc[mt][nt][0], fmaf(a1r, acc[mt][nt][1], prv[mt][0]));
            prv[mt][1] = fmaf(a0r, acc[mt][nt][2], fmaf(a1r, acc[mt][nt][3], prv[mt][1]));
        }
    }
#pragma unroll
    for (int off = 1; off < 4; off <<= 1) {
#pragma unroll
        for (int mt = 0; mt < 4; mt++)
#pragma unroll
            for (int rh = 0; rh < 2; rh++) {
                plv[mt][rh] += __shfl_xor_sync(0xffffffffu, plv[mt][rh], off);
                prv[mt][rh] += __shfl_xor_sync(0xffffffffu, prv[mt][rh], off);
            }
    }
    __syncthreads();
    float* sPL = (float*)sAbuf;          // [2][128]
    float* sPR = (float*)sAbuf + 256;
    if (tg == 0) {
#pragma unroll
        for (int mt = 0; mt < 4; mt++)
#pragma unroll
            for (int rh = 0; rh < 2; rh++) {
                int rowl = wm * 64 + mt * 16 + rh * 8 + g;
                sPL[wn * 128 + rowl] = plv[mt][rh];
                sPR[wn * 128 + rowl] = prv[mt][rh];
            }
    }
    __syncthreads();
    if (tid < 128) {
        int row = bm + tid;
        if (row < NN) {
            g_hl[row * NHEAD + hb] = sPL[tid] + sPL[128 + tid];
            g_hr[row * NHEAD + hb] = sPR[tid] + sPR[128 + tid];
        }
    }
}

// ===== launch 4: single-pass softmax+SpMM; group-max-shifted fp16 accumulate =====
// Per 4-edge group: K = max(e0..e3); v_i = exp(e_i - K) in (0,1] -> fp16 products
// CANNOT overflow (|h| << 16k). Group accumulated with HFMA2, flushed to fp32
// scaled by exp(K). den = fp32 exact: den += exp(K)*(v0+v1+v2+v3).
__global__ __launch_bounds__(256) void aggregate_kernel(float* __restrict__ out) {
    int row = (blockIdx.x * blockDim.x + threadIdx.x) >> 5;
    int lane = threadIdx.x & 31;
    if (row >= NN) return;
    if (lane == 0) g_deg[row] = 0;   // reset for next graph replay
    int start = g_rowptr[row];
    int end = g_rowptr[row + 1];
    float* orow = out + (size_t)row * FEAT + lane * 8;
    if (start == end) {
        float4 z = make_float4(0.f, 0.f, 0.f, 0.f);
        *(float4*)orow = z;
        *(float4*)(orow + 4) = z;
        return;
    }
    int hd = lane >> 3;
    float hlv = g_hl[row * NHEAD + hd];

    float den = 0.f;
    float acc[8] = {0.f, 0.f, 0.f, 0.f, 0.f, 0.f, 0.f, 0.f};
    const size_t fofs = lane * 8;

    int j = start;
    // peel to 16B alignment of g_cols + j (fp32 path)
    int peel = (4 - (start & 3)) & 3;
    if (peel > end - start) peel = end - start;
    for (int t = 0; t < peel; t++, j++) {
        int c = g_cols[j];
        float r = g_hr[c * NHEAD + hd];
        uint4 v = *(const uint4*)(g_hh + (size_t)c * FEAT + fofs);
        float e = hlv + r;
        e = fmaxf(e, ALPHA * e);
        float w = __expf(e);
        den += w;
#pragma unroll
        for (int q = 0; q < 4; q++) {
            unsigned u = (&v.x)[q];
            float2 f = __half22float2(*(__half2*)&u);
            acc[q * 2 + 0] = fmaf(w, f.x, acc[q * 2 + 0]);
            acc[q * 2 + 1] = fmaf(w, f.y, acc[q * 2 + 1]);
        }
    }
    for (; j + 3 < end; j += 4) {
        int4 cc = *(const int4*)(g_cols + j);          // one LDG.128
        int c0 = cc.x, c1 = cc.y, c2 = cc.z, c3 = cc.w;
        float r0 = g_hr[c0 * NHEAD + hd];
        float r1 = g_hr[c1 * NHEAD + hd];
        float r2 = g_hr[c2 * NHEAD + hd];
        float r3 = g_hr[c3 * NHEAD + hd];
        uint4 v0 = *(const uint4*)(g_hh + (size_t)c0 * FEAT + fofs);
        uint4 v1 = *(const uint4*)(g_hh + (size_t)c1 * FEAT + fofs);
        uint4 v2 = *(const uint4*)(g_hh + (size_t)c2 * FEAT + fofs);
        uint4 v3 = *(const uint4*)(g_hh + (size_t)c3 * FEAT + fofs);
        float e0 = hlv + r0; e0 = fmaxf(e0, ALPHA * e0);
        float e1 = hlv + r1; e1 = fmaxf(e1, ALPHA * e1);
        float e2 = hlv + r2; e2 = fmaxf(e2, ALPHA * e2);
        float e3 = hlv + r3; e3 = fmaxf(e3, ALPHA * e3);
        float K = fmaxf(fmaxf(e0, e1), fmaxf(e2, e3));
        float w0 = __expf(e0 - K), w1 = __expf(e1 - K);
        float w2 = __expf(e2 - K), w3 = __expf(e3 - K);
        float eK = __expf(K);
        den = fmaf(eK, (w0 + w1) + (w2 + w3), den);
        __half2 w0h = __float2half2_rn(w0);
        __half2 w1h = __float2half2_rn(w1);
        __half2 w2h = __float2half2_rn(w2);
        __half2 w3h = __float2half2_rn(w3);
#pragma unroll
        for (int q = 0; q < 4; q++) {
            unsigned u0 = (&v0.x)[q], u1 = (&v1.x)[q], u2 = (&v2.x)[q], u3 = (&v3.x)[q];
            __half2 h = __hmul2(*(__half2*)&u0, w0h);
            h = __hfma2(*(__half2*)&u1, w1h, h);
            h = __hfma2(*(__half2*)&u2, w2h, h);
            h = __hfma2(*(__half2*)&u3, w3h, h);
            float2 f = __half22float2(h);
            acc[q * 2 + 0] = fmaf(eK, f.x, acc[q * 2 + 0]);
            acc[q * 2 + 1] = fmaf(eK, f.y, acc[q * 2 + 1]);
        }
    }
    for (; j < end; j++) {
        int c = g_cols[j];
        float r = g_hr[c * NHEAD + hd];
        uint4 v = *(const uint4*)(g_hh + (size_t)c * FEAT + fofs);
        float e = hlv + r;
        e = fmaxf(e, ALPHA * e);
        float w = __expf(e);
        den += w;
#pragma unroll
        for (int q = 0; q < 4; q++) {
            unsigned u = (&v.x)[q];
            float2 f = __half22float2(*(__half2*)&u);
            acc[q * 2 + 0] = fmaf(w, f.x, acc[q * 2 + 0]);
            acc[q * 2 + 1] = fmaf(w, f.y, acc[q * 2 + 1]);
        }
    }
    float inv = 1.0f / den;
    *(float4*)orow = make_float4(acc[0] * inv, acc[1] * inv, acc[2] * inv, acc[3] * inv);
    *(float4*)(orow + 4) = make_float4(acc[4] * inv, acc[5] * inv, acc[6] * inv, acc[7] * inv);
}

// ================= launch =================
extern "C" void kernel_launch(void* const* d_in, const int* in_sizes, int n_in,
                              void* d_out, int out_size) {
    const float* x  = (const float*)d_in[0];
    const int*   eg = (const int*)d_in[1];
    const float* W  = (const float*)d_in[2];
    const float* al = (const float*)d_in[3];
    const float* ar = (const float*)d_in[4];
    float* out = (float*)d_out;

    // 4 launches: hist+prep -> parallel scan -> gemm||scatter -> aggregate(+deg reset)
    hist_prep_kernel<<<HIST_BLOCKS + WF_BLOCKS, 256>>>(eg, W);
    scan_parallel_kernel<<<SCAN_BLOCKS, 256>>>();
    gemm_scatter_kernel<<<GEMM_BLOCKS + (EE + 127) / 128, 128>>>(x, al, ar, eg);
    aggregate_kernel<<<(NN * 32 + 255) / 256, 256>>>(out);
}

// round 16
// speedup vs baseline: 1.0041x; 1.0041x over previous
#include <cuda_runtime.h>
#include <cuda_fp16.h>
#include <math_constants.h>
#include <cstdint>

#define NN   50000
#define EE   800000
#define INF_ 256
#define OUTF 64
#define NHEAD 4
#define FEAT (NHEAD*OUTF)   // 256
#define ALPHA 0.2f

// -------- device scratch (static; allocation-free; zero-initialized) --------
__device__ __half g_hh[(size_t)NN * FEAT];   // projected features, fp16
__device__ float g_hl[NN * NHEAD];
__device__ float g_hr[NN * NHEAD];
__device__ uint2 g_Wf[NHEAD * 16 * 8 * 32];  // W in fp16 mma-fragment order (128KB)
__device__ int   g_deg[NN];                  // reset by aggregate each replay
__device__ int   g_rowptr[NN + 1];
__device__ int   g_cursor[NN];
__device__ int   g_cols[EE];

#define HIST_BLOCKS 3125
#define WF_BLOCKS 64
#define GEMM_BLOCKS 1564        // 4 heads x 391 mtiles
#define GEMM_HALF 782
#define SCAN_TILE 1024
#define SCAN_BLOCKS 49          // ceil(50000/1024)
#define SCATTER_BLOCKS ((EE + 127) / 128)

// ===== launch 1: edge histogram + W fragment prep (blockIdx split) =====
__global__ __launch_bounds__(256) void hist_prep_kernel(const int* __restrict__ edge,
                                                        const float* __restrict__ W) {
    int b = blockIdx.x;
    if (b < HIST_BLOCKS) {
        int e = b * 256 + threadIdx.x;
        if (e < EE) atomicAdd(&g_deg[edge[e]], 1);
    } else {
        int idx = (b - HIST_BLOCKS) * 256 + threadIdx.x;
        if (idx >= NHEAD * 16 * 8 * 32) return;
        int lane = idx & 31;
        int nblk = (idx >> 5) & 7;
        int ks   = (idx >> 8) & 15;
        int hb   = idx >> 12;
        int g = lane >> 2, tg = lane & 3;
        int n = hb * OUTF + nblk * 8 + g;
        int k0 = ks * 16 + 2 * tg;
        __half2 b0 = __floats2half2_rn(W[(size_t)k0 * FEAT + n],
                                       W[(size_t)(k0 + 1) * FEAT + n]);
        __half2 b1 = __floats2half2_rn(W[(size_t)(k0 + 8) * FEAT + n],
                                       W[(size_t)(k0 + 9) * FEAT + n]);
        g_Wf[idx] = make_uint2(*(unsigned*)&b0, *(unsigned*)&b1);
    }
}

// ===== parallel scan tile (128 threads), no inter-block comms =====
__device__ void scan_block_128(int b) {
    __shared__ int s_warp[4];
    __shared__ int s_off;
    int tid = threadIdx.x;
    int lane = tid & 31, w = tid >> 5;
    int tile0 = b * SCAN_TILE;

    // offset = sum of all previous tiles (redundant per block; parallel across blocks)
    int part = 0;
    for (int i = tid; i < tile0; i += 128) part += g_deg[i];
#pragma unroll
    for (int o = 16; o; o >>= 1) part += __shfl_xor_sync(0xffffffffu, part, o);
    if (lane == 0) s_warp[w] = part;
    __syncthreads();
    if (tid == 0) s_off = s_warp[0] + s_warp[1] + s_warp[2] + s_warp[3];
    __syncthreads();
    int offset = s_off;
    __syncthreads();   // s_warp reused

    int i0 = tile0 + tid * 8;
    int v[8];
#pragma unroll
    for (int j = 0; j < 8; j++) {
        int i = i0 + j;
        v[j] = (i < NN) ? g_deg[i] : 0;
    }
#pragma unroll
    for (int j = 1; j < 8; j++) v[j] += v[j - 1];
    int x = v[7];
#pragma unroll
    for (int o = 1; o < 32; o <<= 1) {
        int y = __shfl_up_sync(0xffffffffu, x, o);
        if (lane >= o) x += y;
    }
    if (lane == 31) s_warp[w] = x;
    __syncthreads();
    if (w == 0 && lane < 4) {
        int s = s_warp[lane];
#pragma unroll
        for (int o = 1; o < 4; o <<= 1) {
            int y = __shfl_up_sync(0x0000000fu, s, o);
            if (lane >= o) s += y;
        }
        s_warp[lane] = s;
    }
    __syncthreads();
    int off = offset + (x - v[7]) + (w > 0 ? s_warp[w - 1] : 0);

#pragma unroll
    for (int j = 0; j < 8; j++) {
        int i = i0 + j;
        if (i < NN) {
            g_rowptr[i + 1] = off + v[j];
            g_cursor[i] = off + (j > 0 ? v[j - 1] : 0);
        }
    }
    if (b == 0 && tid == 0) g_rowptr[0] = 0;
}

// ===== shared GEMM block body (fp16 mma, fused hl/hr logits) =====
#define A_STAGE_B 8224   // bytes (2 kst * 4112)

__device__ __forceinline__ void mma_f16(float c[4], unsigned a0, unsigned a1,
                                        unsigned a2, unsigned a3,
                                        unsigned b0, unsigned b1) {
    asm volatile(
        "mma.sync.aligned.m16n8k16.row.col.f32.f16.f16.f32 "
        "{%0,%1,%2,%3}, {%4,%5,%6,%7}, {%8,%9}, {%0,%1,%2,%3};"
        : "+f"(c[0]), "+f"(c[1]), "+f"(c[2]), "+f"(c[3])
        : "r"(a0), "r"(a1), "r"(a2), "r"(a3), "r"(b0), "r"(b1));
}

__device__ __forceinline__ int a_sts_off(int r, int c4) {
    return ((c4 >> 4) ? 4112 : 0) + (r >> 4) * 512 +
           (((r & 7) * 4 + ((c4 & 7) >> 1)) << 4) + (((c4 >> 3) & 1) << 3) +
           (((r >> 3) & 1) << 2);
}

__device__ void gemm_block(int gb, char* sAbuf,
                           const float* __restrict__ X,
                           const float* __restrict__ al,
                           const float* __restrict__ ar) {
    int tid = threadIdx.x;
    int lane = tid & 31;
    int wid = tid >> 5;
    int wm = wid >> 1, wn = wid & 1;
    int g = lane >> 2, tg = lane & 3;
    int hb = gb & 3;                 // head
    int bm = (gb >> 2) * 128;
    int bn = hb * OUTF;

    float acc[4][4][4];
#pragma unroll
    for (int mt = 0; mt < 4; mt++)
#pragma unroll
        for (int nt = 0; nt < 4; nt++)
#pragma unroll
            for (int q = 0; q < 4; q++) acc[mt][nt][q] = 0.f;

    const uint2* Wfb = g_Wf + hb * (16 * 8 * 32);

    uint2 ra[8];
#pragma unroll
    for (int i = 0; i < 8; i++) {
        int f = tid + i * 128;
        int r = f >> 3, c4 = (f & 7) * 4;
        int row = bm + r;
        float4 t = (row < NN) ? *(const float4*)(X + (size_t)row * INF_ + c4)
                              : make_float4(0.f, 0.f, 0.f, 0.f);
        __half2 h0 = __floats2half2_rn(t.x, t.y);
        __half2 h1 = __floats2half2_rn(t.z, t.w);
        ra[i] = make_uint2(*(unsigned*)&h0, *(unsigned*)&h1);
    }
#pragma unroll
    for (int i = 0; i < 8; i++) {
        int f = tid + i * 128;
        int r = f >> 3, c4 = (f & 7) * 4;
        char* p = sAbuf + a_sts_off(r, c4);
        *(unsigned*)p = ra[i].x;
        *(unsigned*)(p + 16) = ra[i].y;
    }
    uint2 bq[4], bqn[4];
#pragma unroll
    for (int nt = 0; nt < 4; nt++)
        bq[nt] = Wfb[(0 * 8 + wn * 4 + nt) * 32 + lane];
    __syncthreads();

    for (int kt = 0; kt < 8; kt++) {
        int st = kt & 1;
        const char* As = sAbuf + st * A_STAGE_B;
        if (kt < 7) {
            int k0 = (kt + 1) * 32;
#pragma unroll
            for (int i = 0; i < 8; i++) {
                int f = tid + i * 128;
                int r = f >> 3, c4 = (f & 7) * 4;
                int row = bm + r;
                float4 t = (row < NN) ? *(const float4*)(X + (size_t)row * INF_ + k0 + c4)
                                      : make_float4(0.f, 0.f, 0.f, 0.f);
                __half2 h0 = __floats2half2_rn(t.x, t.y);
                __half2 h1 = __floats2half2_rn(t.z, t.w);
                ra[i] = make_uint2(*(unsigned*)&h0, *(unsigned*)&h1);
            }
        }
#pragma unroll
        for (int kst = 0; kst < 2; kst++) {
            int ks = kt * 2 + kst;
            if (ks < 15) {
#pragma unroll
                for (int nt = 0; nt < 4; nt++)
                    bqn[nt] = Wfb[((ks + 1) * 8 + wn * 4 + nt) * 32 + lane];
            }
            uint4 af[4];
#pragma unroll
            for (int mt = 0; mt < 4; mt++)
                af[mt] = *(const uint4*)(As + kst * 4112 + (wm * 4 + mt) * 512 +
                                         (g * 4 + tg) * 16);
#pragma unroll
            for (int mt = 0; mt < 4; mt++)
#pragma unroll
                for (int nt = 0; nt < 4; nt++)
                    mma_f16(acc[mt][nt], af[mt].x, af[mt].y, af[mt].z, af[mt].w,
                            bq[nt].x, bq[nt].y);
#pragma unroll
            for (int nt = 0; nt < 4; nt++) bq[nt] = bqn[nt];
        }
        if (kt < 7) {
            char* dA = sAbuf + (1 - st) * A_STAGE_B;
#pragma unroll
            for (int i = 0; i < 8; i++) {
                int f = tid + i * 128;
                int r = f >> 3, c4 = (f & 7) * 4;
                char* p = dA + a_sts_off(r, c4);
                *(unsigned*)p = ra[i].x;
                *(unsigned*)(p + 16) = ra[i].y;
            }
        }
        __syncthreads();
    }

    // epilogue: store h fp16; fused hl/hr logits
    const float* alh = al + hb * OUTF;
    const float* arh = ar + hb * OUTF;
    float plv[4][2] = {{0.f,0.f},{0.f,0.f},{0.f,0.f},{0.f,0.f}};
    float prv[4][2] = {{0.f,0.f},{0.f,0.f},{0.f,0.f},{0.f,0.f}};

#pragma unroll
    for (int mt = 0; mt < 4; mt++) {
#pragma unroll
        for (int nt = 0; nt < 4; nt++) {
            int row0 = bm + wm * 64 + mt * 16 + g;
            int cl = wn * 32 + nt * 8 + tg * 2;
            int col = bn + cl;
            if (row0 < NN)
                *(__half2*)(g_hh + (size_t)row0 * FEAT + col) =
                    __floats2half2_rn(acc[mt][nt][0], acc[mt][nt][1]);
            if (row0 + 8 < NN)
                *(__half2*)(g_hh + (size_t)(row0 + 8) * FEAT + col) =
                    __floats2half2_rn(acc[mt][nt][2], acc[mt][nt][3]);
            float a0l = alh[cl], a1l = alh[cl + 1];
            float a0r = arh[cl], a1r = arh[cl + 1];
            plv[mt][0] = fmaf(a0l, acc[mt][nt][0], fmaf(a1l, acc[mt][nt][1], plv[mt][0]));
            plv[mt][1] = fmaf(a0l, acc[mt][nt][2], fmaf(a1l, acc[mt][nt][3], plv[mt][1]));
            prv[mt][0] = fmaf(a0r, acc[mt][nt][0], fmaf(a1r, acc[mt][nt][1], prv[mt][0]));
            prv[mt][1] = fmaf(a0r, acc[mt][nt][2], fmaf(a1r, acc[mt][nt][3], prv[mt][1]));
        }
    }
#pragma unroll
    for (int off = 1; off < 4; off <<= 1) {
#pragma unroll
        for (int mt = 0; mt < 4; mt++)
#pragma unroll
            for (int rh = 0; rh < 2; rh++) {
                plv[mt][rh] += __shfl_xor_sync(0xffffffffu, plv[mt][rh], off);
                prv[mt][rh] += __shfl_xor_sync(0xffffffffu, prv[mt][rh], off);
            }
    }
    __syncthreads();
    float* sPL = (float*)sAbuf;          // [2][128]
    float* sPR = (float*)sAbuf + 256;
    if (tg == 0) {
#pragma unroll
        for (int mt = 0; mt < 4; mt++)
#pragma unroll
            for (int rh = 0; rh < 2; rh++) {
                int rowl = wm * 64 + mt * 16 + rh * 8 + g;
                sPL[wn * 128 + rowl] = plv[mt][rh];
                sPR[wn * 128 + rowl] = prv[mt][rh];
            }
    }
    __syncthreads();
    if (tid < 128) {
        int row = bm + tid;
        if (row < NN) {
            g_hl[row * NHEAD + hb] = sPL[tid] + sPL[128 + tid];
            g_hr[row * NHEAD + hb] = sPR[tid] + sPR[128 + tid];
        }
    }
}

// ===== launch 2: gemm blocks [0, GEMM_HALF) || parallel scan =====
__global__ __launch_bounds__(128, 4) void gemm_scan_kernel(
    const float* __restrict__ X,
    const float* __restrict__ al, const float* __restrict__ ar) {
    __shared__ __align__(16) char sAbuf[2 * A_STAGE_B];
    if (blockIdx.x < GEMM_HALF) {
        gemm_block(blockIdx.x, sAbuf, X, al, ar);
    } else {
        scan_block_128(blockIdx.x - GEMM_HALF);
    }
}

// ===== launch 3: gemm blocks [GEMM_HALF, GEMM_BLOCKS) || CSR scatter =====
__global__ __launch_bounds__(128, 4) void gemm_scatter_kernel(
    const float* __restrict__ X,
    const float* __restrict__ al, const float* __restrict__ ar,
    const int* __restrict__ edge) {
    __shared__ __align__(16) char sAbuf[2 * A_STAGE_B];
    if (blockIdx.x < GEMM_BLOCKS - GEMM_HALF) {
        gemm_block(GEMM_HALF + blockIdx.x, sAbuf, X, al, ar);
    } else {
        int e = (blockIdx.x - (GEMM_BLOCKS - GEMM_HALF)) * 128 + threadIdx.x;
        if (e < EE) {
            int r = edge[e];
            int c = edge[EE + e];
            int pos = atomicAdd(&g_cursor[r], 1);
            g_cols[pos] = c;
        }
    }
}

// ===== launch 4: single-pass softmax+SpMM (fp32 accumulate, R14 body) =====
__global__ __launch_bounds__(256) void aggregate_kernel(float* __restrict__ out) {
    int row = (blockIdx.x * blockDim.x + threadIdx.x) >> 5;
    int lane = threadIdx.x & 31;
    if (row >= NN) return;
    if (lane == 0) g_deg[row] = 0;   // reset for next graph replay
    int start = g_rowptr[row];
    int end = g_rowptr[row + 1];
    float* orow = out + (size_t)row * FEAT + lane * 8;
    if (start == end) {
        float4 z = make_float4(0.f, 0.f, 0.f, 0.f);
        *(float4*)orow = z;
        *(float4*)(orow + 4) = z;
        return;
    }
    int hd = lane >> 3;
    float hlv = g_hl[row * NHEAD + hd];

    float den = 0.f;
    float acc[8] = {0.f, 0.f, 0.f, 0.f, 0.f, 0.f, 0.f, 0.f};
    const size_t fofs = lane * 8;

    int j = start;
    int peel = (4 - (start & 3)) & 3;
    if (peel > end - start) peel = end - start;
    for (int t = 0; t < peel; t++, j++) {
        int c = g_cols[j];
        float r = g_hr[c * NHEAD + hd];
        uint4 v = *(const uint4*)(g_hh + (size_t)c * FEAT + fofs);
        float e = hlv + r;
        e = fmaxf(e, ALPHA * e);
        float w = __expf(e);
        den += w;
#pragma unroll
        for (int q = 0; q < 4; q++) {
            unsigned u = (&v.x)[q];
            float2 f = __half22float2(*(__half2*)&u);
            acc[q * 2 + 0] = fmaf(w, f.x, acc[q * 2 + 0]);
            acc[q * 2 + 1] = fmaf(w, f.y, acc[q * 2 + 1]);
        }
    }
    for (; j + 3 < end; j += 4) {
        int4 cc = *(const int4*)(g_cols + j);          // one LDG.128
        int c0 = cc.x, c1 = cc.y, c2 = cc.z, c3 = cc.w;
        float r0 = g_hr[c0 * NHEAD + hd];
        float r1 = g_hr[c1 * NHEAD + hd];
        float r2 = g_hr[c2 * NHEAD + hd];
        float r3 = g_hr[c3 * NHEAD + hd];
        uint4 v0 = *(const uint4*)(g_hh + (size_t)c0 * FEAT + fofs);
        uint4 v1 = *(const uint4*)(g_hh + (size_t)c1 * FEAT + fofs);
        uint4 v2 = *(const uint4*)(g_hh + (size_t)c2 * FEAT + fofs);
        uint4 v3 = *(const uint4*)(g_hh + (size_t)c3 * FEAT + fofs);
        float e0 = hlv + r0; e0 = fmaxf(e0, ALPHA * e0);
        float e1 = hlv + r1; e1 = fmaxf(e1, ALPHA * e1);
        float e2 = hlv + r2; e2 = fmaxf(e2, ALPHA * e2);
        float e3 = hlv + r3; e3 = fmaxf(e3, ALPHA * e3);
        float w0 = __expf(e0), w1 = __expf(e1), w2 = __expf(e2), w3 = __expf(e3);
        den += (w0 + w1) + (w2 + w3);
#pragma unroll
        for (int q = 0; q < 4; q++) {
            unsigned u0 = (&v0.x)[q], u1 = (&v1.x)[q], u2 = (&v2.x)[q], u3 = (&v3.x)[q];
            float2 f0 = __half22float2(*(__half2*)&u0);
            float2 f1 = __half22float2(*(__half2*)&u1);
            float2 f2 = __half22float2(*(__half2*)&u2);
            float2 f3 = __half22float2(*(__half2*)&u3);
            acc[q * 2 + 0] = fmaf(w0, f0.x, fmaf(w1, f1.x, fmaf(w2, f2.x,
                             fmaf(w3, f3.x, acc[q * 2 + 0]))));
            acc[q * 2 + 1] = fmaf(w0, f0.y, fmaf(w1, f1.y, fmaf(w2, f2.y,
                             fmaf(w3, f3.y, acc[q * 2 + 1]))));
        }
    }
    for (; j < end; j++) {
        int c = g_cols[j];
        float r = g_hr[c * NHEAD + hd];
        uint4 v = *(const uint4*)(g_hh + (size_t)c * FEAT + fofs);
        float e = hlv + r;
        e = fmaxf(e, ALPHA * e);
        float w = __expf(e);
        den += w;
#pragma unroll
        for (int q = 0; q < 4; q++) {
            unsigned u = (&v.x)[q];
            float2 f = __half22float2(*(__half2*)&u);
            acc[q * 2 + 0] = fmaf(w, f.x, acc[q * 2 + 0]);
            acc[q * 2 + 1] = fmaf(w, f.y, acc[q * 2 + 1]);
        }
    }
    float inv = 1.0f / den;
    *(float4*)orow = make_float4(acc[0] * inv, acc[1] * inv, acc[2] * inv, acc[3] * inv);
    *(float4*)(orow + 4) = make_float4(acc[4] * inv, acc[5] * inv, acc[6] * inv, acc[7] * inv);
}

// ================= launch =================
extern "C" void kernel_launch(void* const* d_in, const int* in_sizes, int n_in,
                              void* d_out, int out_size) {
    const float* x  = (const float*)d_in[0];
    const int*   eg = (const int*)d_in[1];
    const float* W  = (const float*)d_in[2];
    const float* al = (const float*)d_in[3];
    const float* ar = (const float*)d_in[4];
    float* out = (float*)d_out;

    // 4 launches: hist+prep -> gemmA||scan -> gemmB||scatter -> aggregate(+deg reset)
    hist_prep_kernel<<<HIST_BLOCKS + WF_BLOCKS, 256>>>(eg, W);
    gemm_scan_kernel<<<GEMM_HALF + SCAN_BLOCKS, 128>>>(x, al, ar);
    gemm_scatter_kernel<<<(GEMM_BLOCKS - GEMM_HALF) + SCATTER_BLOCKS, 128>>>(x, al, ar, eg);
    aggregate_kernel<<<(NN * 32 + 255) / 256, 256>>>(out);
}

// round 17
// speedup vs baseline: 1.0984x; 1.0939x over previous
#include <cuda_runtime.h>
#include <cuda_fp16.h>
#include <math_constants.h>
#include <cstdint>

#define NN   50000
#define EE   800000
#define INF_ 256
#define OUTF 64
#define NHEAD 4
#define FEAT (NHEAD*OUTF)   // 256
#define ALPHA 0.2f

// -------- device scratch (static; allocation-free; zero-initialized) --------
__device__ __half g_hh[(size_t)NN * FEAT];   // projected features, fp16
__device__ float g_hl[NN * NHEAD];
__device__ float g_hr[NN * NHEAD];
__device__ uint2 g_Wf[NHEAD * 16 * 8 * 32];  // W in fp16 mma-fragment order (128KB)
__device__ int   g_deg[NN];                  // reset by aggregate each replay
__device__ int   g_rowptr[NN + 1];
__device__ int   g_cursor[NN];
__device__ int   g_cols[EE];
__device__ int   g_scan_done;                // reset by aggregate each replay

#define HIST_BLOCKS 782          // 800000 edges / 4-per-thread / 256
#define WF_BLOCKS 64
#define GEMM_BLOCKS 1564         // 4 heads x 391 mtiles
#define SCAN_TILE 1024
#define SCAN_BLOCKS 49           // ceil(50000/1024)
#define SCATTER_BLOCKS ((EE + 127) / 128)

// ===== launch 1: vectorized edge histogram + W fragment prep (blockIdx split) =====
__global__ __launch_bounds__(256) void hist_prep_kernel(const int* __restrict__ edge,
                                                        const float* __restrict__ W) {
    int b = blockIdx.x;
    if (b < HIST_BLOCKS) {
        int t = b * 256 + threadIdx.x;           // 4 edges per thread via int4
        int e0 = t * 4;
        if (e0 < EE) {
            int4 r4 = *(const int4*)(edge + e0);
            atomicAdd(&g_deg[r4.x], 1);
            atomicAdd(&g_deg[r4.y], 1);
            atomicAdd(&g_deg[r4.z], 1);
            atomicAdd(&g_deg[r4.w], 1);
        }
    } else {
        int idx = (b - HIST_BLOCKS) * 256 + threadIdx.x;
        if (idx >= NHEAD * 16 * 8 * 32) return;
        int lane = idx & 31;
        int nblk = (idx >> 5) & 7;
        int ks   = (idx >> 8) & 15;
        int hb   = idx >> 12;
        int g = lane >> 2, tg = lane & 3;
        int n = hb * OUTF + nblk * 8 + g;
        int k0 = ks * 16 + 2 * tg;
        __half2 b0 = __floats2half2_rn(W[(size_t)k0 * FEAT + n],
                                       W[(size_t)(k0 + 1) * FEAT + n]);
        __half2 b1 = __floats2half2_rn(W[(size_t)(k0 + 8) * FEAT + n],
                                       W[(size_t)(k0 + 9) * FEAT + n]);
        g_Wf[idx] = make_uint2(*(unsigned*)&b0, *(unsigned*)&b1);
    }
}

// ===== parallel scan tile (128 threads), no inter-block comms =====
__device__ void scan_block_128(int b) {
    __shared__ int s_warp[4];
    __shared__ int s_off;
    int tid = threadIdx.x;
    int lane = tid & 31, w = tid >> 5;
    int tile0 = b * SCAN_TILE;

    int part = 0;
    for (int i = tid; i < tile0; i += 128) part += g_deg[i];
#pragma unroll
    for (int o = 16; o; o >>= 1) part += __shfl_xor_sync(0xffffffffu, part, o);
    if (lane == 0) s_warp[w] = part;
    __syncthreads();
    if (tid == 0) s_off = s_warp[0] + s_warp[1] + s_warp[2] + s_warp[3];
    __syncthreads();
    int offset = s_off;
    __syncthreads();   // s_warp reused

    int i0 = tile0 + tid * 8;
    int v[8];
#pragma unroll
    for (int j = 0; j < 8; j++) {
        int i = i0 + j;
        v[j] = (i < NN) ? g_deg[i] : 0;
    }
#pragma unroll
    for (int j = 1; j < 8; j++) v[j] += v[j - 1];
    int x = v[7];
#pragma unroll
    for (int o = 1; o < 32; o <<= 1) {
        int y = __shfl_up_sync(0xffffffffu, x, o);
        if (lane >= o) x += y;
    }
    if (lane == 31) s_warp[w] = x;
    __syncthreads();
    if (w == 0 && lane < 4) {
        int s = s_warp[lane];
#pragma unroll
        for (int o = 1; o < 4; o <<= 1) {
            int y = __shfl_up_sync(0x0000000fu, s, o);
            if (lane >= o) s += y;
        }
        s_warp[lane] = s;
    }
    __syncthreads();
    int off = offset + (x - v[7]) + (w > 0 ? s_warp[w - 1] : 0);

#pragma unroll
    for (int j = 0; j < 8; j++) {
        int i = i0 + j;
        if (i < NN) {
            g_rowptr[i + 1] = off + v[j];
            g_cursor[i] = off + (j > 0 ? v[j - 1] : 0);
        }
    }
    if (b == 0 && tid == 0) g_rowptr[0] = 0;

    // publish completion for scatter blocks in this same launch
    __syncthreads();
    __threadfence();
    if (tid == 0) atomicAdd(&g_scan_done, 1);
}

// ===== GEMM block body (fp16 mma, fused hl/hr logits) — unchanged from R14 =====
#define A_STAGE_B 8224   // bytes (2 kst * 4112)

__device__ __forceinline__ void mma_f16(float c[4], unsigned a0, unsigned a1,
                                        unsigned a2, unsigned a3,
                                        unsigned b0, unsigned b1) {
    asm volatile(
        "mma.sync.aligned.m16n8k16.row.col.f32.f16.f16.f32 "
        "{%0,%1,%2,%3}, {%4,%5,%6,%7}, {%8,%9}, {%0,%1,%2,%3};"
        : "+f"(c[0]), "+f"(c[1]), "+f"(c[2]), "+f"(c[3])
        : "r"(a0), "r"(a1), "r"(a2), "r"(a3), "r"(b0), "r"(b1));
}

__device__ __forceinline__ int a_sts_off(int r, int c4) {
    return ((c4 >> 4) ? 4112 : 0) + (r >> 4) * 512 +
           (((r & 7) * 4 + ((c4 & 7) >> 1)) << 4) + (((c4 >> 3) & 1) << 3) +
           (((r >> 3) & 1) << 2);
}

__device__ void gemm_block(int gb, char* sAbuf,
                           const float* __restrict__ X,
                           const float* __restrict__ al,
                           const float* __restrict__ ar) {
    int tid = threadIdx.x;
    int lane = tid & 31;
    int wid = tid >> 5;
    int wm = wid >> 1, wn = wid & 1;
    int g = lane >> 2, tg = lane & 3;
    int hb = gb & 3;                 // head
    int bm = (gb >> 2) * 128;
    int bn = hb * OUTF;

    float acc[4][4][4];
#pragma unroll
    for (int mt = 0; mt < 4; mt++)
#pragma unroll
        for (int nt = 0; nt < 4; nt++)
#pragma unroll
            for (int q = 0; q < 4; q++) acc[mt][nt][q] = 0.f;

    const uint2* Wfb = g_Wf + hb * (16 * 8 * 32);

    uint2 ra[8];
#pragma unroll
    for (int i = 0; i < 8; i++) {
        int f = tid + i * 128;
        int r = f >> 3, c4 = (f & 7) * 4;
        int row = bm + r;
        float4 t = (row < NN) ? *(const float4*)(X + (size_t)row * INF_ + c4)
                              : make_float4(0.f, 0.f, 0.f, 0.f);
        __half2 h0 = __floats2half2_rn(t.x, t.y);
        __half2 h1 = __floats2half2_rn(t.z, t.w);
        ra[i] = make_uint2(*(unsigned*)&h0, *(unsigned*)&h1);
    }
#pragma unroll
    for (int i = 0; i < 8; i++) {
        int f = tid + i * 128;
        int r = f >> 3, c4 = (f & 7) * 4;
        char* p = sAbuf + a_sts_off(r, c4);
        *(unsigned*)p = ra[i].x;
        *(unsigned*)(p + 16) = ra[i].y;
    }
    uint2 bq[4], bqn[4];
#pragma unroll
    for (int nt = 0; nt < 4; nt++)
        bq[nt] = Wfb[(0 * 8 + wn * 4 + nt) * 32 + lane];
    __syncthreads();

    for (int kt = 0; kt < 8; kt++) {
        int st = kt & 1;
        const char* As = sAbuf + st * A_STAGE_B;
        if (kt < 7) {
            int k0 = (kt + 1) * 32;
#pragma unroll
            for (int i = 0; i < 8; i++) {
                int f = tid + i * 128;
                int r = f >> 3, c4 = (f & 7) * 4;
                int row = bm + r;
                float4 t = (row < NN) ? *(const float4*)(X + (size_t)row * INF_ + k0 + c4)
                                      : make_float4(0.f, 0.f, 0.f, 0.f);
                __half2 h0 = __floats2half2_rn(t.x, t.y);
                __half2 h1 = __floats2half2_rn(t.z, t.w);
                ra[i] = make_uint2(*(unsigned*)&h0, *(unsigned*)&h1);
            }
        }
#pragma unroll
        for (int kst = 0; kst < 2; kst++) {
            int ks = kt * 2 + kst;
            if (ks < 15) {
#pragma unroll
                for (int nt = 0; nt < 4; nt++)
                    bqn[nt] = Wfb[((ks + 1) * 8 + wn * 4 + nt) * 32 + lane];
            }
            uint4 af[4];
#pragma unroll
            for (int mt = 0; mt < 4; mt++)
                af[mt] = *(const uint4*)(As + kst * 4112 + (wm * 4 + mt) * 512 +
                                         (g * 4 + tg) * 16);
#pragma unroll
            for (int mt = 0; mt < 4; mt++)
#pragma unroll
                for (int nt = 0; nt < 4; nt++)
                    mma_f16(acc[mt][nt], af[mt].x, af[mt].y, af[mt].z, af[mt].w,
                            bq[nt].x, bq[nt].y);
#pragma unroll
            for (int nt = 0; nt < 4; nt++) bq[nt] = bqn[nt];
        }
        if (kt < 7) {
            char* dA = sAbuf + (1 - st) * A_STAGE_B;
#pragma unroll
            for (int i = 0; i < 8; i++) {
                int f = tid + i * 128;
                int r = f >> 3, c4 = (f & 7) * 4;
                char* p = dA + a_sts_off(r, c4);
                *(unsigned*)p = ra[i].x;
                *(unsigned*)(p + 16) = ra[i].y;
            }
        }
        __syncthreads();
    }

    // epilogue: store h fp16; fused hl/hr logits
    const float* alh = al + hb * OUTF;
    const float* arh = ar + hb * OUTF;
    float plv[4][2] = {{0.f,0.f},{0.f,0.f},{0.f,0.f},{0.f,0.f}};
    float prv[4][2] = {{0.f,0.f},{0.f,0.f},{0.f,0.f},{0.f,0.f}};

#pragma unroll
    for (int mt = 0; mt < 4; mt++) {
#pragma unroll
        for (int nt = 0; nt < 4; nt++) {
            int row0 = bm + wm * 64 + mt * 16 + g;
            int cl = wn * 32 + nt * 8 + tg * 2;
            int col = bn + cl;
            if (row0 < NN)
                *(__half2*)(g_hh + (size_t)row0 * FEAT + col) =
                    __floats2half2_rn(acc[mt][nt][0], acc[mt][nt][1]);
            if (row0 + 8 < NN)
                *(__half2*)(g_hh + (size_t)(row0 + 8) * FEAT + col) =
                    __floats2half2_rn(acc[mt][nt][2], acc[mt][nt][3]);
            float a0l = alh[cl], a1l = alh[cl + 1];
            float a0r = arh[cl], a1r = arh[cl + 1];
            plv[mt][0] = fmaf(a0l, acc[mt][nt][0], fmaf(a1l, acc[mt][nt][1], plv[mt][0]));
            plv[mt][1] = fmaf(a0l, acc[mt][nt][2], fmaf(a1l, acc[mt][nt][3], plv[mt][1]));
            prv[mt][0] = fmaf(a0r, acc[mt][nt][0], fmaf(a1r, acc[mt][nt][1], prv[mt][0]));
            prv[mt][1] = fmaf(a0r, acc[mt][nt][2], fmaf(a1r, acc[mt][nt][3], prv[mt][1]));
        }
    }
#pragma unroll
    for (int off = 1; off < 4; off <<= 1) {
#pragma unroll
        for (int mt = 0; mt < 4; mt++)
#pragma unroll
            for (int rh = 0; rh < 2; rh++) {
                plv[mt][rh] += __shfl_xor_sync(0xffffffffu, plv[mt][rh], off);
                prv[mt][rh] += __shfl_xor_sync(0xffffffffu, prv[mt][rh], off);
            }
    }
    __syncthreads();
    float* sPL = (float*)sAbuf;          // [2][128]
    float* sPR = (float*)sAbuf + 256;
    if (tg == 0) {
#pragma unroll
        for (int mt = 0; mt < 4; mt++)
#pragma unroll
            for (int rh = 0; rh < 2; rh++) {
                int rowl = wm * 64 + mt * 16 + rh * 8 + g;
                sPL[wn * 128 + rowl] = plv[mt][rh];
                sPR[wn * 128 + rowl] = prv[mt][rh];
            }
    }
    __syncthreads();
    if (tid < 128) {
        int row = bm + tid;
        if (row < NN) {
            g_hl[row * NHEAD + hb] = sPL[tid] + sPL[128 + tid];
            g_hr[row * NHEAD + hb] = sPR[tid] + sPR[128 + tid];
        }
    }
}

// ===== launch 2: scan (bid 0-48, wave-1) | gemm | scatter (spins on scan_done) =====
__global__ __launch_bounds__(128, 4) void fused_mid_kernel(
    const float* __restrict__ X,
    const float* __restrict__ al, const float* __restrict__ ar,
    const int* __restrict__ edge) {
    __shared__ __align__(16) char sAbuf[2 * A_STAGE_B];
    int b = blockIdx.x;
    if (b < SCAN_BLOCKS) {
        scan_block_128(b);
        return;
    }
    if (b < SCAN_BLOCKS + GEMM_BLOCKS) {
        gemm_block(b - SCAN_BLOCKS, sAbuf, X, al, ar);
        return;
    }
    // scatter: wait for all scan tiles (scatter blocks land in wave>=2; scan
    // blocks hold the lowest blockIdx and are resident in wave 1 -> spin terminates;
    // in practice it's a single load).
    if (threadIdx.x == 0) {
        while (*(volatile int*)&g_scan_done < SCAN_BLOCKS) { }
    }
    __syncthreads();
    int e = (b - SCAN_BLOCKS - GEMM_BLOCKS) * 128 + threadIdx.x;
    if (e < EE) {
        int r = edge[e];
        int c = edge[EE + e];
        int pos = atomicAdd(&g_cursor[r], 1);
        g_cols[pos] = c;
    }
}

// ===== launch 3: single-pass softmax+SpMM (fp32 accumulate, R14 body) =====
__global__ __launch_bounds__(256) void aggregate_kernel(float* __restrict__ out) {
    int row = (blockIdx.x * blockDim.x + threadIdx.x) >> 5;
    int lane = threadIdx.x & 31;
    if (blockIdx.x == 0 && threadIdx.x == 0) g_scan_done = 0;  // reset for next replay
    if (row >= NN) return;
    if (lane == 0) g_deg[row] = 0;   // reset for next graph replay
    int start = g_rowptr[row];
    int end = g_rowptr[row + 1];
    float* orow = out + (size_t)row * FEAT + lane * 8;
    if (start == end) {
        float4 z = make_float4(0.f, 0.f, 0.f, 0.f);
        *(float4*)orow = z;
        *(float4*)(orow + 4) = z;
        return;
    }
    int hd = lane >> 3;
    float hlv = g_hl[row * NHEAD + hd];

    float den = 0.f;
    float acc[8] = {0.f, 0.f, 0.f, 0.f, 0.f, 0.f, 0.f, 0.f};
    const size_t fofs = lane * 8;

    int j = start;
    int peel = (4 - (start & 3)) & 3;
    if (peel > end - start) peel = end - start;
    for (int t = 0; t < peel; t++, j++) {
        int c = g_cols[j];
        float r = g_hr[c * NHEAD + hd];
        uint4 v = *(const uint4*)(g_hh + (size_t)c * FEAT + fofs);
        float e = hlv + r;
        e = fmaxf(e, ALPHA * e);
        float w = __expf(e);
        den += w;
#pragma unroll
        for (int q = 0; q < 4; q++) {
            unsigned u = (&v.x)[q];
            float2 f = __half22float2(*(__half2*)&u);
            acc[q * 2 + 0] = fmaf(w, f.x, acc[q * 2 + 0]);
            acc[q * 2 + 1] = fmaf(w, f.y, acc[q * 2 + 1]);
        }
    }
    for (; j + 3 < end; j += 4) {
        int4 cc = *(const int4*)(g_cols + j);          // one LDG.128
        int c0 = cc.x, c1 = cc.y, c2 = cc.z, c3 = cc.w;
        float r0 = g_hr[c0 * NHEAD + hd];
        float r1 = g_hr[c1 * NHEAD + hd];
        float r2 = g_hr[c2 * NHEAD + hd];
        float r3 = g_hr[c3 * NHEAD + hd];
        uint4 v0 = *(const uint4*)(g_hh + (size_t)c0 * FEAT + fofs);
        uint4 v1 = *(const uint4*)(g_hh + (size_t)c1 * FEAT + fofs);
        uint4 v2 = *(const uint4*)(g_hh + (size_t)c2 * FEAT + fofs);
        uint4 v3 = *(const uint4*)(g_hh + (size_t)c3 * FEAT + fofs);
        float e0 = hlv + r0; e0 = fmaxf(e0, ALPHA * e0);
        float e1 = hlv + r1; e1 = fmaxf(e1, ALPHA * e1);
        float e2 = hlv + r2; e2 = fmaxf(e2, ALPHA * e2);
        float e3 = hlv + r3; e3 = fmaxf(e3, ALPHA * e3);
        float w0 = __expf(e0), w1 = __expf(e1), w2 = __expf(e2), w3 = __expf(e3);
        den += (w0 + w1) + (w2 + w3);
#pragma unroll
        for (int q = 0; q < 4; q++) {
            unsigned u0 = (&v0.x)[q], u1 = (&v1.x)[q], u2 = (&v2.x)[q], u3 = (&v3.x)[q];
            float2 f0 = __half22float2(*(__half2*)&u0);
            float2 f1 = __half22float2(*(__half2*)&u1);
            float2 f2 = __half22float2(*(__half2*)&u2);
            float2 f3 = __half22float2(*(__half2*)&u3);
            acc[q * 2 + 0] = fmaf(w0, f0.x, fmaf(w1, f1.x, fmaf(w2, f2.x,
                             fmaf(w3, f3.x, acc[q * 2 + 0]))));
            acc[q * 2 + 1] = fmaf(w0, f0.y, fmaf(w1, f1.y, fmaf(w2, f2.y,
                             fmaf(w3, f3.y, acc[q * 2 + 1]))));
        }
    }
    for (; j < end; j++) {
        int c = g_cols[j];
        float r = g_hr[c * NHEAD + hd];
        uint4 v = *(const uint4*)(g_hh + (size_t)c * FEAT + fofs);
        float e = hlv + r;
        e = fmaxf(e, ALPHA * e);
        float w = __expf(e);
        den += w;
#pragma unroll
        for (int q = 0; q < 4; q++) {
            unsigned u = (&v.x)[q];
            float2 f = __half22float2(*(__half2*)&u);
            acc[q * 2 + 0] = fmaf(w, f.x, acc[q * 2 + 0]);
            acc[q * 2 + 1] = fmaf(w, f.y, acc[q * 2 + 1]);
        }
    }
    float inv = 1.0f / den;
    *(float4*)orow = make_float4(acc[0] * inv, acc[1] * inv, acc[2] * inv, acc[3] * inv);
    *(float4*)(orow + 4) = make_float4(acc[4] * inv, acc[5] * inv, acc[6] * inv, acc[7] * inv);
}

// ================= launch =================
extern "C" void kernel_launch(void* const* d_in, const int* in_sizes, int n_in,
                              void* d_out, int out_size) {
    const float* x  = (const float*)d_in[0];
    const int*   eg = (const int*)d_in[1];
    const float* W  = (const float*)d_in[2];
    const float* al = (const float*)d_in[3];
    const float* ar = (const float*)d_in[4];
    float* out = (float*)d_out;

    // 3 launches: hist+prep -> scan|gemm|scatter (internally ordered) -> aggregate
    hist_prep_kernel<<<HIST_BLOCKS + WF_BLOCKS, 256>>>(eg, W);
    fused_mid_kernel<<<SCAN_BLOCKS + GEMM_BLOCKS + SCATTER_BLOCKS, 128>>>(x, al, ar, eg);
    aggregate_kernel<<<(NN * 32 + 255) / 256, 256>>>(out);
}